// round 4
// baseline (speedup 1.0000x reference)
#include <cuda_runtime.h>
#include <cuda_bf16.h>

// KVGather: out[b,i,t] = kv[b, r_idx[b,i,t]] * r_weight[b,i,t]
// n=32, p2=49, topk=4, hw=64, c=256
// Inputs (metadata order): r_idx (n,p2,topk) int32 OR int64 (auto-detected),
//                          r_weight f32 (n,p2,topk), kv f32 (n,p2,hw,c).
// Output f32 (n,p2,topk,hw,c).

#define N_B   32
#define P2    49
#define TOPK  4
#define HW    64
#define CKV   256
#define TILE_V4   4096                  // 64*256/4 float4s per tile (64 KB)
#define THREADS   256
#define V4_PER_T  (TILE_V4 / THREADS)   // 16
#define NCHUNK    (N_B * P2 * TOPK)     // 6272

// 1 = r_idx is int32 (one word per element), 0 = int64 (two words, low word holds value)
__device__ int g_idx_is_i32;

// Single-CTA detector. Scans ONLY the first NCHUNK int32 words (in-bounds for
// both dtypes: int32 buffer = NCHUNK words, int64 buffer = 2*NCHUNK words).
//  - int64 data: odd words are high halves of values in [0,49) -> all zero.
//  - int32 data: odd words are 3136 uniform indices in [0,49);
//    all-zero has probability 49^-3136 ~= 0.
// Any nonzero odd word => int32.
__global__ void detect_idx_dtype_kernel(const int* __restrict__ idx_words)
{
    __shared__ int s_any;
    if (threadIdx.x == 0) s_any = 0;
    __syncthreads();

    int any = 0;
    for (int i = 1 + 2 * threadIdx.x; i < NCHUNK; i += 2 * blockDim.x)
        any |= idx_words[i];
    if (any) atomicOr(&s_any, 1);
    __syncthreads();

    if (threadIdx.x == 0) g_idx_is_i32 = (s_any != 0) ? 1 : 0;
}

__global__ __launch_bounds__(THREADS)
void kvgather_kernel(const int*    __restrict__ idx_words,
                     const float*  __restrict__ r_weight,
                     const float4* __restrict__ kv,
                     float4*       __restrict__ out)
{
    const int chunk = blockIdx.x;            // b*P2*TOPK + i*TOPK + t
    const int b     = chunk / (P2 * TOPK);

    // Uniform per-CTA scalars (same address across the CTA -> broadcast)
    const int is32 = g_idx_is_i32;
    int idx = is32 ? idx_words[chunk] : idx_words[2 * chunk];
    // Defensive clamp: never generate an OOB address.
    idx = (idx < 0) ? 0 : (idx >= P2 ? P2 - 1 : idx);
    const float w = r_weight[chunk];

    const float4* __restrict__ src = kv  + ((long long)b * P2 + idx) * TILE_V4;
    float4*       __restrict__ dst = out + (long long)chunk * TILE_V4;

    const int t = threadIdx.x;
    #pragma unroll
    for (int k = 0; k < V4_PER_T; ++k) {
        const int off = t + k * THREADS;
        float4 v = __ldg(&src[off]);
        v.x *= w; v.y *= w; v.z *= w; v.w *= w;
        dst[off] = v;
    }
}

extern "C" void kernel_launch(void* const* d_in, const int* in_sizes, int n_in,
                              void* d_out, int out_size)
{
    const int*    idx_words = (const int*)d_in[0];
    const float*  r_weight  = (const float*)d_in[1];
    const float4* kv        = (const float4*)d_in[2];
    float4*       out       = (float4*)d_out;

    detect_idx_dtype_kernel<<<1, 256>>>(idx_words);
    kvgather_kernel<<<NCHUNK, THREADS>>>(idx_words, r_weight, kv, out);
}

// round 6
// speedup vs baseline: 1.0185x; 1.0185x over previous
#include <cuda_runtime.h>
#include <cuda_bf16.h>

// KVGather: out[b,i,t] = kv[b, r_idx[b,i,t]] * r_weight[b,i,t]
// n=32, p2=49, topk=4, hw=64, c=256
// Inputs (metadata order): r_idx int32 (n,p2,topk)  [confirmed: int64 read crashed
//   in R1, int32 auto-detect passed with rel_err=0 in R4],
//   r_weight f32 (n,p2,topk), kv f32 (n,p2,hw,c).
// Output f32 (n,p2,topk,hw,c).

#define N_B   32
#define P2    49
#define TOPK  4
#define HW    64
#define CKV   256
#define TILE_V4   4096                  // 64*256/4 float4s per tile (64 KB)
#define THREADS   256
#define V4_PER_T  (TILE_V4 / THREADS)   // 16
#define NCHUNK    (N_B * P2 * TOPK)     // 6272

__global__ __launch_bounds__(THREADS)
void kvgather_kernel(const int*    __restrict__ r_idx,
                     const float*  __restrict__ r_weight,
                     const float4* __restrict__ kv,
                     float4*       __restrict__ out)
{
    const int chunk = blockIdx.x;            // b*P2*TOPK + i*TOPK + t
    const int b     = chunk / (P2 * TOPK);

    // Uniform per-CTA scalars (same address across the CTA -> broadcast)
    int idx = r_idx[chunk];                  // 0 <= idx < P2
    // Defensive clamp: never generate an OOB address even if idx is corrupt.
    idx = (idx < 0) ? 0 : (idx >= P2 ? P2 - 1 : idx);
    const float w = r_weight[chunk];

    const float4* __restrict__ src = kv  + ((long long)b * P2 + idx) * TILE_V4;
    float4*       __restrict__ dst = out + (long long)chunk * TILE_V4;

    const int t = threadIdx.x;
    #pragma unroll
    for (int k = 0; k < V4_PER_T; ++k) {
        const int off = t + k * THREADS;
        float4 v = __ldg(&src[off]);
        v.x *= w; v.y *= w; v.z *= w; v.w *= w;
        // Streaming store: output is write-once, never re-read. Evict-first in
        // L2 so the 411 MB output stream doesn't evict the reused kv tiles.
        __stcs(&dst[off], v);
    }
}

extern "C" void kernel_launch(void* const* d_in, const int* in_sizes, int n_in,
                              void* d_out, int out_size)
{
    const int*    r_idx    = (const int*)d_in[0];
    const float*  r_weight = (const float*)d_in[1];
    const float4* kv       = (const float4*)d_in[2];
    float4*       out      = (float4*)d_out;

    kvgather_kernel<<<NCHUNK, THREADS>>>(r_idx, r_weight, kv, out);
}